// round 7
// baseline (speedup 1.0000x reference)
#include <cuda_runtime.h>
#include <stdint.h>

// ---------------------------------------------------------------------------
// Attention3D, tf32 tensor cores + cp.async pipelines.
// All tensor operands rna-rounded to tf32 before global memory.
//   0) prep: round x, qkv_w, proj_w
//   1) QKV GEMM -> Q/K natural, V transposed [hb][c][key]
//   2) flash attention Br=64 Bc=64, 128-thread CTAs (4 warps), 97KB smem,
//      2 CTAs/SM with no register cap; K+V double buffered, 1 sync/iter
//   3) proj GEMM -> d_out
// ---------------------------------------------------------------------------

#define NHB  24
#define NSEQ 2048
#define HD   64
#define CDIM 768

__device__ float g_q[NHB * NSEQ * HD];
__device__ float g_k[NHB * NSEQ * HD];
__device__ float g_v[NHB * HD * NSEQ];        // [hb][c][key]
__device__ float g_attnout[4096 * CDIM];
__device__ float g_xr[4096 * CDIM];
__device__ float g_qkvw[CDIM * 2304];
__device__ float g_projw[CDIM * CDIM];

// --- helpers ---------------------------------------------------------------
__device__ __forceinline__ uint32_t f2tf32(float x) {
    uint32_t u;
    asm("cvt.rna.tf32.f32 %0, %1;" : "=r"(u) : "f"(x));
    return u;
}
__device__ __forceinline__ float rtf(float x) {
    return __uint_as_float(f2tf32(x));
}
__device__ __forceinline__ void cpa16(float* dst, const float* src) {
    uint32_t d = (uint32_t)__cvta_generic_to_shared(dst);
    asm volatile("cp.async.cg.shared.global [%0], [%1], 16;" :: "r"(d), "l"(src));
}
__device__ __forceinline__ void cp_commit() {
    asm volatile("cp.async.commit_group;");
}
__device__ __forceinline__ void cp_wait0() {
    asm volatile("cp.async.wait_group 0;");
}
__device__ __forceinline__ void ldsm4(uint32_t r[4], const float* p) {
    uint32_t a = (uint32_t)__cvta_generic_to_shared(p);
    asm volatile("ldmatrix.sync.aligned.m8n8.x4.shared.b16 {%0,%1,%2,%3}, [%4];"
                 : "=r"(r[0]), "=r"(r[1]), "=r"(r[2]), "=r"(r[3]) : "r"(a));
}
__device__ __forceinline__ void mma8(float d[4], const uint32_t a[4],
                                     uint32_t b0, uint32_t b1) {
    asm volatile(
        "mma.sync.aligned.m16n8k8.row.col.f32.tf32.tf32.f32 "
        "{%0,%1,%2,%3}, {%4,%5,%6,%7}, {%8,%9}, {%0,%1,%2,%3};"
        : "+f"(d[0]), "+f"(d[1]), "+f"(d[2]), "+f"(d[3])
        : "r"(a[0]), "r"(a[1]), "r"(a[2]), "r"(a[3]), "r"(b0), "r"(b1));
}

// ---------------------------------------------------------------------------
// Prep: rna-round inputs into scratch.
// ---------------------------------------------------------------------------
__global__ void __launch_bounds__(256) prep_round(
    const float* __restrict__ x, const float* __restrict__ qw,
    const float* __restrict__ pw)
{
    const int stride = gridDim.x * 256;
    const int t = blockIdx.x * 256 + threadIdx.x;
    for (int f = t; f < (4096 * CDIM) / 4; f += stride) {
        float4 v = *(const float4*)&x[f * 4];
        *(float4*)&g_xr[f * 4] = make_float4(rtf(v.x), rtf(v.y), rtf(v.z), rtf(v.w));
    }
    for (int f = t; f < (CDIM * 2304) / 4; f += stride) {
        float4 v = *(const float4*)&qw[f * 4];
        *(float4*)&g_qkvw[f * 4] = make_float4(rtf(v.x), rtf(v.y), rtf(v.z), rtf(v.w));
    }
    for (int f = t; f < (CDIM * CDIM) / 4; f += stride) {
        float4 v = *(const float4*)&pw[f * 4];
        *(float4*)&g_projw[f * 4] = make_float4(rtf(v.x), rtf(v.y), rtf(v.z), rtf(v.w));
    }
}

// ---------------------------------------------------------------------------
// tf32 GEMM, 128x128 k16, 2-stage cp.async (pre-rounded sources).
// ---------------------------------------------------------------------------
template <int MODE>
__global__ void __launch_bounds__(256) mm_tf32(
    const float* __restrict__ bias, float* __restrict__ out)
{
    constexpr int N = (MODE == 0) ? 2304 : 768;
    __shared__ float As[2][128 * 20];
    __shared__ float Bs[2][16 * 136];
    const int tid = threadIdx.x, lane = tid & 31, w = tid >> 5;
    const int wm = w >> 1, wn = w & 1;
    const int bm = blockIdx.x * 128, bn = blockIdx.y * 128;
    const float* Ap = (MODE == 0) ? g_xr : g_attnout;
    const float* W_ = (MODE == 0) ? g_qkvw : g_projw;

    float c[2][8][4];
#pragma unroll
    for (int i = 0; i < 2; i++)
#pragma unroll
        for (int j = 0; j < 8; j++)
#pragma unroll
            for (int k = 0; k < 4; k++) c[i][j][k] = 0.f;

    auto stage = [&](int k0, int buf) {
#pragma unroll
        for (int it = 0; it < 2; it++) {
            const int i = tid + it * 256;
            const int r = i >> 2, c4 = (i & 3) << 2;
            cpa16(&As[buf][r * 20 + c4], &Ap[(bm + r) * 768 + k0 + c4]);
        }
#pragma unroll
        for (int it = 0; it < 2; it++) {
            const int i = tid + it * 256;
            const int kk = i >> 5, n4 = (i & 31) << 2;
            cpa16(&Bs[buf][kk * 136 + n4], &W_[(k0 + kk) * N + bn + n4]);
        }
    };

    stage(0, 0); cp_commit();

    int buf = 0;
    for (int k0 = 0; k0 < 768; k0 += 16, buf ^= 1) {
        cp_wait0();
        __syncthreads();
        if (k0 + 16 < 768) { stage(k0 + 16, buf ^ 1); cp_commit(); }

        const uint32_t* bp = (const uint32_t*)Bs[buf];
#pragma unroll
        for (int ks = 0; ks < 2; ks++) {
            uint32_t a0[4], a1[4];
            ldsm4(a0, &As[buf][(wm * 32 + ((lane >> 3) & 1) * 8 + (lane & 7)) * 20
                               + ks * 8 + (lane >> 4) * 4]);
            ldsm4(a1, &As[buf][(wm * 32 + 16 + ((lane >> 3) & 1) * 8 + (lane & 7)) * 20
                               + ks * 8 + (lane >> 4) * 4]);
#pragma unroll
            for (int nt = 0; nt < 8; nt++) {
                const int ncol = wn * 64 + nt * 8 + (lane >> 2);
                uint32_t b0 = bp[(ks * 8 + (lane & 3)) * 136 + ncol];
                uint32_t b1 = bp[(ks * 8 + 4 + (lane & 3)) * 136 + ncol];
                mma8(c[0][nt], a0, b0, b1);
                mma8(c[1][nt], a1, b0, b1);
            }
        }
        __syncthreads();
    }

    if (MODE == 0) {
        const int hc = bn + wn * 64;
        const int which = hc / 768;
        const int head = (hc % 768) >> 6;
#pragma unroll
        for (int mt = 0; mt < 2; mt++)
#pragma unroll
            for (int nt = 0; nt < 8; nt++) {
                const int ccol = nt * 8 + ((lane & 3) << 1);
                const float b0v = bias[hc + ccol];
                const float b1v = bias[hc + ccol + 1];
#pragma unroll
                for (int h = 0; h < 2; h++) {
                    const int row = bm + wm * 32 + mt * 16 + (lane >> 2) + 8 * h;
                    const int b_ = row >> 11, n = row & 2047;
                    const int hb = b_ * 12 + head;
                    const float v0 = rtf(c[mt][nt][2 * h] + b0v);
                    const float v1 = rtf(c[mt][nt][2 * h + 1] + b1v);
                    if (which == 0)
                        *(float2*)&g_q[((hb * NSEQ + n) << 6) + ccol] = make_float2(v0, v1);
                    else if (which == 1)
                        *(float2*)&g_k[((hb * NSEQ + n) << 6) + ccol] = make_float2(v0, v1);
                    else {
                        g_v[hb * (HD * NSEQ) + ccol * NSEQ + n] = v0;
                        g_v[hb * (HD * NSEQ) + (ccol + 1) * NSEQ + n] = v1;
                    }
                }
            }
    } else {
#pragma unroll
        for (int mt = 0; mt < 2; mt++)
#pragma unroll
            for (int nt = 0; nt < 8; nt++) {
                const int col = bn + wn * 64 + nt * 8 + ((lane & 3) << 1);
                const float b0v = bias[col], b1v = bias[col + 1];
#pragma unroll
                for (int h = 0; h < 2; h++) {
                    const int row = bm + wm * 32 + mt * 16 + (lane >> 2) + 8 * h;
                    *(float2*)&out[row * 768 + col] =
                        make_float2(c[mt][nt][2 * h] + b0v, c[mt][nt][2 * h + 1] + b1v);
                }
            }
    }
}

// ---------------------------------------------------------------------------
// Flash attention: Br=64, Bc=64, 128 threads (4 warps, 16 q-rows each).
// smem floats: Qs/Ps overlay 64x68 | Ks 2x64x68 | Vt 2x64x68 |
//              rDt 8x64 | rHt 16x64 | rWt 16x64  = 24320 fl = 97280 B
// K+V double buffered, ONE commit group and ONE __syncthreads per iter.
// ---------------------------------------------------------------------------
#define QS_OFF 0
#define KS_OFF 4352
#define VT_OFF 13056
#define RD_OFF 21760
#define RH_OFF 22272
#define RW_OFF 23296
#define FL_FLOATS 24320
#define FL_BYTES  (FL_FLOATS * 4)

__global__ void __launch_bounds__(128) flash_kernel(
    const float* __restrict__ rpd, const float* __restrict__ rph,
    const float* __restrict__ rpw)
{
    extern __shared__ float sm[];
    float* Qs  = sm + QS_OFF;     // prologue only
    float* Ps  = sm + QS_OFF;     // main loop overlay (warp-private rows)
    float* Ks  = sm + KS_OFF;
    float* Vt  = sm + VT_OFF;
    float* rDt = sm + RD_OFF;
    float* rHt = sm + RH_OFF;
    float* rWt = sm + RW_OFF;

    const int tid = threadIdx.x, lane = tid & 31, w = tid >> 5;   // w 0..3
    const int hb = blockIdx.y;
    const int qbase = blockIdx.x * 64;
    const float scale = 0.125f;

    auto stageKV = [&](int kt, int buf) {
        const float* Kg = &g_k[(hb * NSEQ + kt * 64) * HD];
        const float* Vg = &g_v[hb * (HD * NSEQ) + kt * 64];
        float* Kb = Ks + buf * 4352;
        float* Vb = Vt + buf * 4352;
#pragma unroll
        for (int it = 0; it < 8; it++) {
            const int f = it * 512 + tid * 4;     // 64*64 floats
            const int r = f >> 6, c0 = f & 63;
            cpa16(&Kb[r * 68 + c0], &Kg[f]);
            cpa16(&Vb[r * 68 + c0], &Vg[r * NSEQ + c0]);
        }
    };

    stageKV(0, 0); cp_commit();

    // --- stage Q (pre-rounded bits) ---
    const float* Qg = &g_q[(hb * NSEQ + qbase) * HD];
#pragma unroll
    for (int it = 0; it < 8; it++) {
        const int f = it * 512 + tid * 4;         // 64*64
        const int r = f >> 6, c0 = f & 63;
        *(float4*)&Qs[r * 68 + c0] = *(const float4*)&Qg[f];
    }
    __syncthreads();

    // --- rel-pos tables for this block's 64 queries ---
    for (int i = tid; i < 64 * 40; i += 128) {
        const int row = i / 40, j = i - row * 40;
        const int n = qbase + row;
        const int d = n >> 8, h = (n >> 4) & 15, wq = n & 15;
        const float* trow;
        float* dst;
        if (j < 8)       { trow = &rpd[(d - j + 7) * HD];        dst = &rDt[j * 64 + row]; }
        else if (j < 24) { const int kh = j - 8;  trow = &rph[(h - kh + 15) * HD];  dst = &rHt[kh * 64 + row]; }
        else             { const int kw = j - 24; trow = &rpw[(wq - kw + 15) * HD]; dst = &rWt[kw * 64 + row]; }
        const float* qrow = &Qs[row * 68];
        float s = 0.f;
#pragma unroll
        for (int c = 0; c < HD; c++) s += qrow[c] * trow[c];
        *dst = s;
    }
    __syncthreads();   // tables + Qs visible everywhere

    // --- hoist Q A-fragments (Qs intact until first Ps write) ---
    uint32_t aq[8][4];
#pragma unroll
    for (int ks = 0; ks < 8; ks++)
        ldsm4(aq[ks], &Qs[(w * 16 + ((lane >> 3) & 1) * 8 + (lane & 7)) * 68
                          + ks * 8 + (lane >> 4) * 4]);
    int rq[2];
    rq[0] = w * 16 + (lane >> 2);
    rq[1] = rq[0] + 8;
    float rw[2][2][2];
#pragma unroll
    for (int p = 0; p < 2; p++)
#pragma unroll
        for (int j2 = 0; j2 < 2; j2++)
#pragma unroll
            for (int h = 0; h < 2; h++)
                rw[p][j2][h] = rWt[(8 * p + 2 * (lane & 3) + j2) * 64 + rq[h]];

    float m[2] = {-1e30f, -1e30f}, l[2] = {0.f, 0.f};
    float o[8][4];
#pragma unroll
    for (int i = 0; i < 8; i++)
#pragma unroll
        for (int j = 0; j < 4; j++) o[i][j] = 0.f;

    int buf = 0;
    for (int kt = 0; kt < 32; kt++, buf ^= 1) {
        cp_wait0();               // K/V tile kt resident
        __syncthreads();          // visible to all; prev iter fully done
        if (kt + 1 < 32) { stageKV(kt + 1, buf ^ 1); cp_commit(); }
        const float* Kb = Ks + buf * 4352;
        const float* Vb = Vt + buf * 4352;

        // --- S = Q K^T ---
        float s[8][4];
#pragma unroll
        for (int i = 0; i < 8; i++)
#pragma unroll
            for (int j = 0; j < 4; j++) s[i][j] = 0.f;
#pragma unroll
        for (int ksp = 0; ksp < 4; ksp++) {
#pragma unroll
            for (int nt = 0; nt < 8; nt++) {
                uint32_t k4[4];
                ldsm4(k4, &Kb[(nt * 8 + (lane & 7)) * 68 + ksp * 16 + (lane >> 3) * 4]);
                mma8(s[nt], aq[2 * ksp], k4[0], k4[1]);
                mma8(s[nt], aq[2 * ksp + 1], k4[2], k4[3]);
            }
        }

        // --- scale + bias ---
        const int kd = kt >> 2;
        float bh[4][2];
#pragma unroll
        for (int g = 0; g < 4; g++)
#pragma unroll
            for (int h = 0; h < 2; h++)
                bh[g][h] = rDt[kd * 64 + rq[h]]
                         + rHt[((kt & 3) * 4 + g) * 64 + rq[h]];
#pragma unroll
        for (int nt = 0; nt < 8; nt++)
#pragma unroll
            for (int h = 0; h < 2; h++)
#pragma unroll
                for (int j2 = 0; j2 < 2; j2++)
                    s[nt][2 * h + j2] = fmaf(s[nt][2 * h + j2], scale,
                                             bh[nt >> 1][h] + rw[nt & 1][j2][h]);

        // --- online softmax ---
#pragma unroll
        for (int h = 0; h < 2; h++) {
            float rmax = s[0][2 * h];
#pragma unroll
            for (int nt = 0; nt < 8; nt++) {
                rmax = fmaxf(rmax, s[nt][2 * h]);
                rmax = fmaxf(rmax, s[nt][2 * h + 1]);
            }
            rmax = fmaxf(rmax, __shfl_xor_sync(0xffffffffu, rmax, 1));
            rmax = fmaxf(rmax, __shfl_xor_sync(0xffffffffu, rmax, 2));
            const float mn = fmaxf(m[h], rmax);
            const float corr = __expf(m[h] - mn);
            m[h] = mn;
            float rs = 0.f;
#pragma unroll
            for (int nt = 0; nt < 8; nt++) {
                s[nt][2 * h]     = __expf(s[nt][2 * h] - mn);
                s[nt][2 * h + 1] = __expf(s[nt][2 * h + 1] - mn);
                rs += s[nt][2 * h] + s[nt][2 * h + 1];
            }
            rs += __shfl_xor_sync(0xffffffffu, rs, 1);
            rs += __shfl_xor_sync(0xffffffffu, rs, 2);
            l[h] = l[h] * corr + rs;
#pragma unroll
            for (int nt = 0; nt < 8; nt++) {
                o[nt][2 * h] *= corr;
                o[nt][2 * h + 1] *= corr;
            }
        }

        // --- store P (rna tf32) to warp-private Ps rows ---
#pragma unroll
        for (int nt = 0; nt < 8; nt++)
#pragma unroll
            for (int h = 0; h < 2; h++) {
                uint2 pv = make_uint2(f2tf32(s[nt][2 * h]), f2tf32(s[nt][2 * h + 1]));
                *(uint2*)&Ps[(w * 16 + (lane >> 2) + 8 * h) * 68
                             + nt * 8 + 2 * (lane & 3)] = pv;
            }
        __syncwarp();             // warp-private rows: warp sync suffices

        // --- O += P V ---
#pragma unroll
        for (int ksp = 0; ksp < 4; ksp++) {
            uint32_t ap0[4], ap1[4];
            ldsm4(ap0, &Ps[(w * 16 + ((lane >> 3) & 1) * 8 + (lane & 7)) * 68
                           + ksp * 16 + (lane >> 4) * 4]);
            ldsm4(ap1, &Ps[(w * 16 + ((lane >> 3) & 1) * 8 + (lane & 7)) * 68
                           + ksp * 16 + 8 + (lane >> 4) * 4]);
#pragma unroll
            for (int nt = 0; nt < 8; nt++) {
                uint32_t v4[4];
                ldsm4(v4, &Vb[(nt * 8 + (lane & 7)) * 68 + ksp * 16 + (lane >> 3) * 4]);
                mma8(o[nt], ap0, v4[0], v4[1]);
                mma8(o[nt], ap1, v4[2], v4[3]);
            }
        }
    }

    // --- finalize (rna-rounded: feeds proj as tf32 A operand) ---
    const int b = hb / 12, head = hb % 12;
#pragma unroll
    for (int h = 0; h < 2; h++) {
        const float inv = 1.0f / l[h];
        const int qg = qbase + rq[h];
        float* orow = &g_attnout[(b * NSEQ + qg) * CDIM + head * 64];
#pragma unroll
        for (int nt = 0; nt < 8; nt++)
            *(float2*)&orow[nt * 8 + 2 * (lane & 3)] =
                make_float2(rtf(o[nt][2 * h] * inv), rtf(o[nt][2 * h + 1] * inv));
    }
}

// ---------------------------------------------------------------------------
extern "C" void kernel_launch(void* const* d_in, const int* in_sizes, int n_in,
                              void* d_out, int out_size)
{
    const float* x      = (const float*)d_in[0];
    const float* qkv_w  = (const float*)d_in[1];
    const float* qkv_b  = (const float*)d_in[2];
    const float* proj_w = (const float*)d_in[3];
    const float* proj_b = (const float*)d_in[4];
    const float* rpd    = (const float*)d_in[5];
    const float* rph    = (const float*)d_in[6];
    const float* rpw    = (const float*)d_in[7];
    float* out = (float*)d_out;

    cudaFuncSetAttribute(flash_kernel,
                         cudaFuncAttributeMaxDynamicSharedMemorySize, FL_BYTES);

    prep_round<<<1184, 256>>>(x, qkv_w, proj_w);
    mm_tf32<0><<<dim3(32, 18), 256>>>(qkv_b, nullptr);
    flash_kernel<<<dim3(32, NHB), 128, FL_BYTES>>>(rpd, rph, rpw);
    mm_tf32<1><<<dim3(32, 6), 256>>>(proj_b, out);
}

// round 8
// speedup vs baseline: 1.0568x; 1.0568x over previous
#include <cuda_runtime.h>
#include <stdint.h>

// ---------------------------------------------------------------------------
// Attention3D, tf32 tensor cores + cp.async pipelines.
// All tensor operands rna-rounded to tf32 before global memory.
//   0) prep: round x, qkv_w, proj_w
//   1) QKV GEMM -> Q/K natural, V transposed [hb][c][key]
//   2) flash attention Br=128 Bc=64, 8 warps, 3-deep K/V ring:
//      S(kt+1) mma issued BEFORE softmax(kt) so tensor pipe drains under it
//   3) proj GEMM -> d_out
// ---------------------------------------------------------------------------

#define NHB  24
#define NSEQ 2048
#define HD   64
#define CDIM 768

__device__ float g_q[NHB * NSEQ * HD];
__device__ float g_k[NHB * NSEQ * HD];
__device__ float g_v[NHB * HD * NSEQ];        // [hb][c][key]
__device__ float g_attnout[4096 * CDIM];
__device__ float g_xr[4096 * CDIM];
__device__ float g_qkvw[CDIM * 2304];
__device__ float g_projw[CDIM * CDIM];

// --- helpers ---------------------------------------------------------------
__device__ __forceinline__ uint32_t f2tf32(float x) {
    uint32_t u;
    asm("cvt.rna.tf32.f32 %0, %1;" : "=r"(u) : "f"(x));
    return u;
}
__device__ __forceinline__ float rtf(float x) {
    return __uint_as_float(f2tf32(x));
}
__device__ __forceinline__ void cpa16(float* dst, const float* src) {
    uint32_t d = (uint32_t)__cvta_generic_to_shared(dst);
    asm volatile("cp.async.cg.shared.global [%0], [%1], 16;" :: "r"(d), "l"(src));
}
__device__ __forceinline__ void cp_commit() {
    asm volatile("cp.async.commit_group;");
}
__device__ __forceinline__ void cp_wait0() {
    asm volatile("cp.async.wait_group 0;");
}
__device__ __forceinline__ void cp_wait1() {
    asm volatile("cp.async.wait_group 1;");
}
__device__ __forceinline__ void ldsm4(uint32_t r[4], const float* p) {
    uint32_t a = (uint32_t)__cvta_generic_to_shared(p);
    asm volatile("ldmatrix.sync.aligned.m8n8.x4.shared.b16 {%0,%1,%2,%3}, [%4];"
                 : "=r"(r[0]), "=r"(r[1]), "=r"(r[2]), "=r"(r[3]) : "r"(a));
}
__device__ __forceinline__ void mma8(float d[4], const uint32_t a[4],
                                     uint32_t b0, uint32_t b1) {
    asm volatile(
        "mma.sync.aligned.m16n8k8.row.col.f32.tf32.tf32.f32 "
        "{%0,%1,%2,%3}, {%4,%5,%6,%7}, {%8,%9}, {%0,%1,%2,%3};"
        : "+f"(d[0]), "+f"(d[1]), "+f"(d[2]), "+f"(d[3])
        : "r"(a[0]), "r"(a[1]), "r"(a[2]), "r"(a[3]), "r"(b0), "r"(b1));
}

// ---------------------------------------------------------------------------
// Prep: rna-round inputs into scratch.
// ---------------------------------------------------------------------------
__global__ void __launch_bounds__(256) prep_round(
    const float* __restrict__ x, const float* __restrict__ qw,
    const float* __restrict__ pw)
{
    const int stride = gridDim.x * 256;
    const int t = blockIdx.x * 256 + threadIdx.x;
    for (int f = t; f < (4096 * CDIM) / 4; f += stride) {
        float4 v = *(const float4*)&x[f * 4];
        *(float4*)&g_xr[f * 4] = make_float4(rtf(v.x), rtf(v.y), rtf(v.z), rtf(v.w));
    }
    for (int f = t; f < (CDIM * 2304) / 4; f += stride) {
        float4 v = *(const float4*)&qw[f * 4];
        *(float4*)&g_qkvw[f * 4] = make_float4(rtf(v.x), rtf(v.y), rtf(v.z), rtf(v.w));
    }
    for (int f = t; f < (CDIM * CDIM) / 4; f += stride) {
        float4 v = *(const float4*)&pw[f * 4];
        *(float4*)&g_projw[f * 4] = make_float4(rtf(v.x), rtf(v.y), rtf(v.z), rtf(v.w));
    }
}

// ---------------------------------------------------------------------------
// tf32 GEMM, 128x128 k16, 2-stage cp.async (pre-rounded sources).
// ---------------------------------------------------------------------------
template <int MODE>
__global__ void __launch_bounds__(256) mm_tf32(
    const float* __restrict__ bias, float* __restrict__ out)
{
    constexpr int N = (MODE == 0) ? 2304 : 768;
    __shared__ float As[2][128 * 20];
    __shared__ float Bs[2][16 * 136];
    const int tid = threadIdx.x, lane = tid & 31, w = tid >> 5;
    const int wm = w >> 1, wn = w & 1;
    const int bm = blockIdx.x * 128, bn = blockIdx.y * 128;
    const float* Ap = (MODE == 0) ? g_xr : g_attnout;
    const float* W_ = (MODE == 0) ? g_qkvw : g_projw;

    float c[2][8][4];
#pragma unroll
    for (int i = 0; i < 2; i++)
#pragma unroll
        for (int j = 0; j < 8; j++)
#pragma unroll
            for (int k = 0; k < 4; k++) c[i][j][k] = 0.f;

    auto stage = [&](int k0, int buf) {
#pragma unroll
        for (int it = 0; it < 2; it++) {
            const int i = tid + it * 256;
            const int r = i >> 2, c4 = (i & 3) << 2;
            cpa16(&As[buf][r * 20 + c4], &Ap[(bm + r) * 768 + k0 + c4]);
        }
#pragma unroll
        for (int it = 0; it < 2; it++) {
            const int i = tid + it * 256;
            const int kk = i >> 5, n4 = (i & 31) << 2;
            cpa16(&Bs[buf][kk * 136 + n4], &W_[(k0 + kk) * N + bn + n4]);
        }
    };

    stage(0, 0); cp_commit();

    int buf = 0;
    for (int k0 = 0; k0 < 768; k0 += 16, buf ^= 1) {
        cp_wait0();
        __syncthreads();
        if (k0 + 16 < 768) { stage(k0 + 16, buf ^ 1); cp_commit(); }

        const uint32_t* bp = (const uint32_t*)Bs[buf];
#pragma unroll
        for (int ks = 0; ks < 2; ks++) {
            uint32_t a0[4], a1[4];
            ldsm4(a0, &As[buf][(wm * 32 + ((lane >> 3) & 1) * 8 + (lane & 7)) * 20
                               + ks * 8 + (lane >> 4) * 4]);
            ldsm4(a1, &As[buf][(wm * 32 + 16 + ((lane >> 3) & 1) * 8 + (lane & 7)) * 20
                               + ks * 8 + (lane >> 4) * 4]);
#pragma unroll
            for (int nt = 0; nt < 8; nt++) {
                const int ncol = wn * 64 + nt * 8 + (lane >> 2);
                uint32_t b0 = bp[(ks * 8 + (lane & 3)) * 136 + ncol];
                uint32_t b1 = bp[(ks * 8 + 4 + (lane & 3)) * 136 + ncol];
                mma8(c[0][nt], a0, b0, b1);
                mma8(c[1][nt], a1, b0, b1);
            }
        }
        __syncthreads();
    }

    if (MODE == 0) {
        const int hc = bn + wn * 64;
        const int which = hc / 768;
        const int head = (hc % 768) >> 6;
#pragma unroll
        for (int mt = 0; mt < 2; mt++)
#pragma unroll
            for (int nt = 0; nt < 8; nt++) {
                const int ccol = nt * 8 + ((lane & 3) << 1);
                const float b0v = bias[hc + ccol];
                const float b1v = bias[hc + ccol + 1];
#pragma unroll
                for (int h = 0; h < 2; h++) {
                    const int row = bm + wm * 32 + mt * 16 + (lane >> 2) + 8 * h;
                    const int b_ = row >> 11, n = row & 2047;
                    const int hb = b_ * 12 + head;
                    const float v0 = rtf(c[mt][nt][2 * h] + b0v);
                    const float v1 = rtf(c[mt][nt][2 * h + 1] + b1v);
                    if (which == 0)
                        *(float2*)&g_q[((hb * NSEQ + n) << 6) + ccol] = make_float2(v0, v1);
                    else if (which == 1)
                        *(float2*)&g_k[((hb * NSEQ + n) << 6) + ccol] = make_float2(v0, v1);
                    else {
                        g_v[hb * (HD * NSEQ) + ccol * NSEQ + n] = v0;
                        g_v[hb * (HD * NSEQ) + (ccol + 1) * NSEQ + n] = v1;
                    }
                }
            }
    } else {
#pragma unroll
        for (int mt = 0; mt < 2; mt++)
#pragma unroll
            for (int nt = 0; nt < 8; nt++) {
                const int col = bn + wn * 64 + nt * 8 + ((lane & 3) << 1);
                const float b0v = bias[col], b1v = bias[col + 1];
#pragma unroll
                for (int h = 0; h < 2; h++) {
                    const int row = bm + wm * 32 + mt * 16 + (lane >> 2) + 8 * h;
                    *(float2*)&out[row * 768 + col] =
                        make_float2(c[mt][nt][2 * h] + b0v, c[mt][nt][2 * h + 1] + b1v);
                }
            }
    }
}

// ---------------------------------------------------------------------------
// Flash attention: Br=128, Bc=64, 256 threads (8 warps, 16 q-rows each).
// 3-deep K/V ring (prefetch distance 2).  S(kt+1) mma issued before
// softmax(kt): in-order issue enqueues HMMA, then ALU/MUFU softmax runs
// while the tensor pipe drains.  One __syncthreads per iteration.
// smem floats: Qs/Ps overlay 128x68 | K ring 3x64x68 | V ring 3x64x68 |
//              rDt 8x128 | rHt 16x128 | rWt 16x128  = 39936 fl = 159744 B
// ---------------------------------------------------------------------------
#define QS_OFF 0
#define KS_OFF 8704
#define VT_OFF 21760
#define RD_OFF 34816
#define RH_OFF 35840
#define RW_OFF 37888
#define FL_FLOATS 39936
#define FL_BYTES  (FL_FLOATS * 4)

__global__ void __launch_bounds__(256) flash_kernel(
    const float* __restrict__ rpd, const float* __restrict__ rph,
    const float* __restrict__ rpw)
{
    extern __shared__ float sm[];
    float* Qs  = sm + QS_OFF;     // prologue only
    float* Ps  = sm + QS_OFF;     // main loop overlay (warp-private rows)
    float* Ks  = sm + KS_OFF;
    float* Vt  = sm + VT_OFF;
    float* rDt = sm + RD_OFF;
    float* rHt = sm + RH_OFF;
    float* rWt = sm + RW_OFF;

    const int tid = threadIdx.x, lane = tid & 31, w = tid >> 5;
    const int hb = blockIdx.y;
    const int qbase = blockIdx.x * 128;
    const float scale = 0.125f;

    auto stageKV = [&](int kt, int ring) {
        const float* Kg = &g_k[(hb * NSEQ + kt * 64) * HD];
        const float* Vg = &g_v[hb * (HD * NSEQ) + kt * 64];
        float* Kb = Ks + ring * 4352;
        float* Vb = Vt + ring * 4352;
#pragma unroll
        for (int it = 0; it < 4; it++) {
            const int f = it * 1024 + tid * 4;    // 64*64 floats
            const int r = f >> 6, c0 = f & 63;
            cpa16(&Kb[r * 68 + c0], &Kg[f]);
            cpa16(&Vb[r * 68 + c0], &Vg[r * NSEQ + c0]);
        }
    };

    stageKV(0, 0); cp_commit();
    stageKV(1, 1); cp_commit();

    // --- stage Q (pre-rounded bits) ---
    const float* Qg = &g_q[(hb * NSEQ + qbase) * HD];
#pragma unroll
    for (int it = 0; it < 8; it++) {
        const int f = it * 1024 + tid * 4;        // 128*64
        const int r = f >> 6, c0 = f & 63;
        *(float4*)&Qs[r * 68 + c0] = *(const float4*)&Qg[f];
    }
    __syncthreads();

    // --- rel-pos tables for this block's 128 queries ---
    for (int i = tid; i < 128 * 40; i += 256) {
        const int row = i / 40, j = i - row * 40;
        const int n = qbase + row;
        const int d = n >> 8, h = (n >> 4) & 15, wq = n & 15;
        const float* trow;
        float* dst;
        if (j < 8)       { trow = &rpd[(d - j + 7) * HD];        dst = &rDt[j * 128 + row]; }
        else if (j < 24) { const int kh = j - 8;  trow = &rph[(h - kh + 15) * HD];  dst = &rHt[kh * 128 + row]; }
        else             { const int kw = j - 24; trow = &rpw[(wq - kw + 15) * HD]; dst = &rWt[kw * 128 + row]; }
        const float* qrow = &Qs[row * 68];
        float s = 0.f;
#pragma unroll
        for (int c = 0; c < HD; c++) s += qrow[c] * trow[c];
        *dst = s;
    }
    __syncthreads();   // tables + Qs visible everywhere

    // --- hoist Q A-fragments + per-thread rW values ---
    uint32_t aq[8][4];
#pragma unroll
    for (int ks = 0; ks < 8; ks++)
        ldsm4(aq[ks], &Qs[(w * 16 + ((lane >> 3) & 1) * 8 + (lane & 7)) * 68
                          + ks * 8 + (lane >> 4) * 4]);
    int rq[2];
    rq[0] = w * 16 + (lane >> 2);
    rq[1] = rq[0] + 8;
    float rw[2][2][2];
#pragma unroll
    for (int p = 0; p < 2; p++)
#pragma unroll
        for (int j2 = 0; j2 < 2; j2++)
#pragma unroll
            for (int h = 0; h < 2; h++)
                rw[p][j2][h] = rWt[(8 * p + 2 * (lane & 3) + j2) * 128 + rq[h]];

    auto computeS = [&](const float* Kb, float s[8][4]) {
#pragma unroll
        for (int i = 0; i < 8; i++)
#pragma unroll
            for (int j = 0; j < 4; j++) s[i][j] = 0.f;
#pragma unroll
        for (int ksp = 0; ksp < 4; ksp++) {
#pragma unroll
            for (int nt = 0; nt < 8; nt++) {
                uint32_t k4[4];
                ldsm4(k4, &Kb[(nt * 8 + (lane & 7)) * 68 + ksp * 16 + (lane >> 3) * 4]);
                mma8(s[nt], aq[2 * ksp], k4[0], k4[1]);
                mma8(s[nt], aq[2 * ksp + 1], k4[2], k4[3]);
            }
        }
    };

    float m[2] = {-1e30f, -1e30f}, l[2] = {0.f, 0.f};
    float o[8][4];
#pragma unroll
    for (int i = 0; i < 8; i++)
#pragma unroll
        for (int j = 0; j < 4; j++) o[i][j] = 0.f;

    // --- prologue S for tile 0 ---
    float s_cur[8][4], s_next[8][4];
    cp_wait1();            // group 0 (K0/V0) resident
    __syncthreads();
    computeS(Ks, s_cur);

    for (int kt = 0; kt < 32; kt++) {
        const float* Vb = Vt + (kt % 3) * 4352;
        cp_wait0();        // all committed groups (up to kt+1) resident
        __syncthreads();   // all warps past iter kt-1 (ring WAR safe)
        if (kt + 2 < 32) { stageKV(kt + 2, (kt + 2) % 3); cp_commit(); }

        // --- issue S(kt+1) FIRST: tensor pipe drains under softmax(kt) ---
        if (kt + 1 < 32) computeS(Ks + ((kt + 1) % 3) * 4352, s_next);

        // --- scale + bias on s_cur (tile kt) ---
        const int kd = kt >> 2;
        float bh[4][2];
#pragma unroll
        for (int g = 0; g < 4; g++)
#pragma unroll
            for (int h = 0; h < 2; h++)
                bh[g][h] = rDt[kd * 128 + rq[h]]
                         + rHt[((kt & 3) * 4 + g) * 128 + rq[h]];
#pragma unroll
        for (int nt = 0; nt < 8; nt++)
#pragma unroll
            for (int h = 0; h < 2; h++)
#pragma unroll
                for (int j2 = 0; j2 < 2; j2++)
                    s_cur[nt][2 * h + j2] = fmaf(s_cur[nt][2 * h + j2], scale,
                                                 bh[nt >> 1][h] + rw[nt & 1][j2][h]);

        // --- online softmax ---
#pragma unroll
        for (int h = 0; h < 2; h++) {
            float rmax = s_cur[0][2 * h];
#pragma unroll
            for (int nt = 0; nt < 8; nt++) {
                rmax = fmaxf(rmax, s_cur[nt][2 * h]);
                rmax = fmaxf(rmax, s_cur[nt][2 * h + 1]);
            }
            rmax = fmaxf(rmax, __shfl_xor_sync(0xffffffffu, rmax, 1));
            rmax = fmaxf(rmax, __shfl_xor_sync(0xffffffffu, rmax, 2));
            const float mn = fmaxf(m[h], rmax);
            const float corr = __expf(m[h] - mn);
            m[h] = mn;
            float rs = 0.f;
#pragma unroll
            for (int nt = 0; nt < 8; nt++) {
                s_cur[nt][2 * h]     = __expf(s_cur[nt][2 * h] - mn);
                s_cur[nt][2 * h + 1] = __expf(s_cur[nt][2 * h + 1] - mn);
                rs += s_cur[nt][2 * h] + s_cur[nt][2 * h + 1];
            }
            rs += __shfl_xor_sync(0xffffffffu, rs, 1);
            rs += __shfl_xor_sync(0xffffffffu, rs, 2);
            l[h] = l[h] * corr + rs;
#pragma unroll
            for (int nt = 0; nt < 8; nt++) {
                o[nt][2 * h] *= corr;
                o[nt][2 * h + 1] *= corr;
            }
        }

        // --- store P (rna tf32) to warp-private Ps rows ---
#pragma unroll
        for (int nt = 0; nt < 8; nt++)
#pragma unroll
            for (int h = 0; h < 2; h++) {
                uint2 pv = make_uint2(f2tf32(s_cur[nt][2 * h]),
                                      f2tf32(s_cur[nt][2 * h + 1]));
                *(uint2*)&Ps[(w * 16 + (lane >> 2) + 8 * h) * 68
                             + nt * 8 + 2 * (lane & 3)] = pv;
            }
        __syncwarp();

        // --- O += P V(kt) ---
#pragma unroll
        for (int ksp = 0; ksp < 4; ksp++) {
            uint32_t ap0[4], ap1[4];
            ldsm4(ap0, &Ps[(w * 16 + ((lane >> 3) & 1) * 8 + (lane & 7)) * 68
                           + ksp * 16 + (lane >> 4) * 4]);
            ldsm4(ap1, &Ps[(w * 16 + ((lane >> 3) & 1) * 8 + (lane & 7)) * 68
                           + ksp * 16 + 8 + (lane >> 4) * 4]);
#pragma unroll
            for (int nt = 0; nt < 8; nt++) {
                uint32_t v4[4];
                ldsm4(v4, &Vb[(nt * 8 + (lane & 7)) * 68 + ksp * 16 + (lane >> 3) * 4]);
                mma8(o[nt], ap0, v4[0], v4[1]);
                mma8(o[nt], ap1, v4[2], v4[3]);
            }
        }

        // rotate S
#pragma unroll
        for (int i = 0; i < 8; i++)
#pragma unroll
            for (int j = 0; j < 4; j++) s_cur[i][j] = s_next[i][j];
    }

    // --- finalize (rna-rounded: feeds proj as tf32 A operand) ---
    const int b = hb / 12, head = hb % 12;
#pragma unroll
    for (int h = 0; h < 2; h++) {
        const float inv = 1.0f / l[h];
        const int qg = qbase + rq[h];
        float* orow = &g_attnout[(b * NSEQ + qg) * CDIM + head * 64];
#pragma unroll
        for (int nt = 0; nt < 8; nt++)
            *(float2*)&orow[nt * 8 + 2 * (lane & 3)] =
                make_float2(rtf(o[nt][2 * h] * inv), rtf(o[nt][2 * h + 1] * inv));
    }
}

// ---------------------------------------------------------------------------
extern "C" void kernel_launch(void* const* d_in, const int* in_sizes, int n_in,
                              void* d_out, int out_size)
{
    const float* x      = (const float*)d_in[0];
    const float* qkv_w  = (const float*)d_in[1];
    const float* qkv_b  = (const float*)d_in[2];
    const float* proj_w = (const float*)d_in[3];
    const float* proj_b = (const float*)d_in[4];
    const float* rpd    = (const float*)d_in[5];
    const float* rph    = (const float*)d_in[6];
    const float* rpw    = (const float*)d_in[7];
    float* out = (float*)d_out;

    cudaFuncSetAttribute(flash_kernel,
                         cudaFuncAttributeMaxDynamicSharedMemorySize, FL_BYTES);

    prep_round<<<1184, 256>>>(x, qkv_w, proj_w);
    mm_tf32<0><<<dim3(32, 18), 256>>>(qkv_b, nullptr);
    flash_kernel<<<dim3(16, NHB), 256, FL_BYTES>>>(rpd, rph, rpw);
    mm_tf32<1><<<dim3(32, 6), 256>>>(proj_b, out);
}